// round 14
// baseline (speedup 1.0000x reference)
#include <cuda_runtime.h>
#include <cuda_bf16.h>
#include <math.h>
#include <stdint.h>

// Problem constants
#define BS 128
#define NN 2000
#define DD 256
#define HH 8
#define HDIM 32
#define CCTX 64
#define CNODE 8
#define TANH_CLIP 10.0f

#define SPLIT 20          // n-splits for k3
#define RS (NN / SPLIT)   // 100 rows per k3 block
#define TR 20             // tile rows in k3
#define NTILES (RS / TR)  // 5
#define RPW (TR / 4)      // 5 rows per warp per tile

#define SPLIT1 25          // n-splits for k1
#define RPB1 (NN / SPLIT1) // 80

#define SPLITL 25         // n-splits for k5
#define RSL (NN / SPLITL) // 80 rows per k5a block (= 8 warps * 10 rows exactly)

#define INV_SQRT_HD 0.17677669529663687f   // 1/sqrt(32)
#define INV_SQRT_D  0.0625f                // 1/sqrt(256)

typedef unsigned long long u64;

// ---------------- scratch (16B aligned) ----------------
__device__ __align__(16) float g_sump[BS * SPLIT1 * DD];
__device__ __align__(16) float g_qk[BS * HH * DD];
__device__ __align__(16) float g_qn[BS * HH * CNODE];
__device__ __align__(16) float g_pm[BS * SPLIT * HH];
__device__ __align__(16) float g_pl[BS * SPLIT * HH];
__device__ __align__(16) float g_paw[BS * SPLIT * HH * DD];
__device__ __align__(16) float g_panf[BS * SPLIT * HH * CNODE];
__device__ __align__(16) float g_aw[BS * HH * DD];
__device__ __align__(16) float g_anfc[BS * HH * CNODE];
__device__ __align__(16) float g_g2[BS * DD];
__device__ __align__(16) float g_gn[BS * CNODE];
__device__ __align__(16) float g_tl[BS * NN];      // exp(clipped logit), 0 if masked
__device__ __align__(16) float g_psum[BS * SPLITL];
__device__ int g_flags;   // zero-initialized at load; atomicOr idempotent across replays

// ---------------- helpers ----------------
__device__ __forceinline__ void cp_async16(void* sdst, const void* gsrc) {
    unsigned s = (unsigned)__cvta_generic_to_shared(sdst);
    asm volatile("cp.async.cg.shared.global [%0], [%1], 16;\n" :: "r"(s), "l"(gsrc) : "memory");
}
#define CP_COMMIT asm volatile("cp.async.commit_group;\n" ::: "memory")
#define CP_WAIT1  asm volatile("cp.async.wait_group 1;\n" ::: "memory")
#define CP_WAIT0  asm volatile("cp.async.wait_group 0;\n" ::: "memory")
#define FULLM 0xffffffffu

// packed fp32x2 (Blackwell FFMA2 — PTX-only path)
__device__ __forceinline__ u64 fma2(u64 a, u64 b, u64 c) {
    u64 d; asm("fma.rn.f32x2 %0, %1, %2, %3;" : "=l"(d) : "l"(a), "l"(b), "l"(c)); return d;
}
__device__ __forceinline__ u64 mul2(u64 a, u64 b) {
    u64 d; asm("mul.rn.f32x2 %0, %1, %2;" : "=l"(d) : "l"(a), "l"(b)); return d;
}
__device__ __forceinline__ u64 pk2(float lo, float hi) {
    u64 r; asm("mov.b64 %0, {%1, %2};" : "=l"(r) : "f"(lo), "f"(hi)); return r;
}
__device__ __forceinline__ float hsum2(u64 v) {
    float lo, hi; asm("mov.b64 {%0, %1}, %2;" : "=f"(lo), "=f"(hi) : "l"(v)); return lo + hi;
}

__device__ __forceinline__ bool read_mask(const void* mp, int flags, size_t i) {
    if (flags == 0) return false;
    if (flags & 2) {
        if (flags & 1) return ((const unsigned char*)mp)[i] != 0;  // bool
        return ((const float*)mp)[i] != 0.0f;                      // float32
    }
    return ((const int*)mp)[i] != 0;                               // int32
}

// ---------------- K1: per-split partial sums of enc + mask scan ----------------
// grid (BS, SPLIT1), block 256. Front-batched 20-deep independent loads.
__global__ __launch_bounds__(256) void k1_sum(const float* __restrict__ enc,
                                              const void* __restrict__ maskp) {
    __shared__ __align__(16) float4 sred[256];
    int b = blockIdx.x, s = blockIdx.y;
    int tid = threadIdx.x;
    int c4 = tid & 63;
    int rg = tid >> 6;

    const float4* base = (const float4*)(enc + ((size_t)b * NN + (size_t)s * RPB1) * DD) + c4;
    float4 acc = make_float4(0.f, 0.f, 0.f, 0.f);
#pragma unroll
    for (int r = 0; r < RPB1 / 4; r++) {
        float4 v = base[(size_t)(rg + 4 * r) * 64];
        acc.x += v.x; acc.y += v.y; acc.z += v.z; acc.w += v.w;
    }
    sred[tid] = acc;
    __syncthreads();
    if (tid < 64) {
        float4 a = sred[tid], b1 = sred[tid + 64], c = sred[tid + 128], d = sred[tid + 192];
        float4 r;
        r.x = a.x + b1.x + c.x + d.x;
        r.y = a.y + b1.y + c.y + d.y;
        r.z = a.z + b1.z + c.z + d.z;
        r.w = a.w + b1.w + c.w + d.w;
        ((float4*)&g_sump[(b * SPLIT1 + s) * DD])[c4] = r;
    }

    size_t idx = (size_t)(b * SPLIT1 + s) * 256 + tid;
    bool nz0 = false, nz1 = false;
    if (idx < (size_t)BS * NN) {
        unsigned char v = ((const unsigned char*)maskp)[idx];
        if (v) { if ((idx & 3) == 0) nz0 = true; else nz1 = true; }
    }
    unsigned b0 = __ballot_sync(FULLM, nz0);
    unsigned b1 = __ballot_sync(FULLM, nz1);
    if ((tid & 31) == 0) {
        int f = (b0 ? 1 : 0) | (b1 ? 2 : 0);
        if (f) atomicOr(&g_flags, f);
    }
}

// ---------------- K2: per-batch setup (coalesced warp-GEMV) ----------------
// grid BS, block 256
__global__ __launch_bounds__(256) void k2_setup(const float* __restrict__ shelf,
                                                const float* __restrict__ ctx,
                                                const float* __restrict__ Wk,
                                                const float* __restrict__ Wq,
                                                const float* __restrict__ Wc,
                                                const float* __restrict__ Wg,
                                                const float* __restrict__ Wn,
                                                const int* __restrict__ cur_node) {
    __shared__ __align__(16) float Xs[2 * DD];
    __shared__ __align__(16) float Qs[DD];
    __shared__ __align__(16) float ms[DD];
    int b = blockIdx.x, t = threadIdx.x;
    int w = t >> 5, lane = t & 31;

    int cn = cur_node[b];
    Xs[t] = shelf[((size_t)b * NN + cn) * DD + t];
    float a = 0.0f;
#pragma unroll 8
    for (int c = 0; c < CCTX; c++) a += ctx[b * CCTX + c] * Wc[t * CCTX + c];
    Xs[DD + t] = a;
    float smv = 0.0f;
#pragma unroll
    for (int s = 0; s < SPLIT1; s++) smv += g_sump[(b * SPLIT1 + s) * DD + t];
    ms[t] = smv * (1.0f / NN);
    __syncthreads();

    {
        float msr[8];
        const float4* msp = (const float4*)ms + lane * 2;
        { float4 v0 = msp[0], v1 = msp[1];
          msr[0]=v0.x; msr[1]=v0.y; msr[2]=v0.z; msr[3]=v0.w;
          msr[4]=v1.x; msr[5]=v1.y; msr[6]=v1.z; msr[7]=v1.w; }
        float xr[16];
        const float4* xp = (const float4*)Xs + lane * 4;
#pragma unroll
        for (int j = 0; j < 4; j++) {
            float4 v = xp[j];
            xr[j*4+0]=v.x; xr[j*4+1]=v.y; xr[j*4+2]=v.z; xr[j*4+3]=v.w;
        }
#pragma unroll 4
        for (int o = 0; o < 32; o++) {
            int tt = w * 32 + o;
            const float4* wg4 = (const float4*)(Wg + (size_t)tt * DD) + lane * 2;
            const float4* wq4 = (const float4*)(Wq + (size_t)tt * 2 * DD) + lane * 4;
            float acc = 0.0f;
            float4 g0 = wg4[0], g1 = wg4[1];
            acc += msr[0]*g0.x + msr[1]*g0.y + msr[2]*g0.z + msr[3]*g0.w;
            acc += msr[4]*g1.x + msr[5]*g1.y + msr[6]*g1.z + msr[7]*g1.w;
#pragma unroll
            for (int j = 0; j < 4; j++) {
                float4 q4 = wq4[j];
                acc += xr[j*4+0]*q4.x + xr[j*4+1]*q4.y + xr[j*4+2]*q4.z + xr[j*4+3]*q4.w;
            }
#pragma unroll
            for (int o2 = 16; o2 > 0; o2 >>= 1) acc += __shfl_xor_sync(FULLM, acc, o2);
            if (lane == 0) Qs[tt] = acc;
        }
    }
    __syncthreads();

#pragma unroll
    for (int h = 0; h < HH; h++) {
        float a2 = 0.0f;
#pragma unroll 8
        for (int e = 0; e < HDIM; e++) a2 += Qs[h * HDIM + e] * Wk[(h * HDIM + e) * DD + t];
        g_qk[(b * HH + h) * DD + t] = a2 * INV_SQRT_HD;
    }
    if (t < HH * CNODE) {
        int h = t >> 3, c = t & 7;
        float a3 = 0.0f;
#pragma unroll 8
        for (int e = 0; e < HDIM; e++) a3 += Qs[h * HDIM + e] * Wn[(h * HDIM + e) * CNODE + c];
        g_qn[(b * HH + h) * CNODE + c] = a3 * INV_SQRT_HD;
    }
}

// ---------------- K3: split flash glimpse, deferred per-tile rescale ----------------
// grid (BS, SPLIT), block 256
__global__ __launch_bounds__(256, 2) void k3_attn(const float* __restrict__ enc,
                                                  const float* __restrict__ nf) {
    __shared__ __align__(16) float encS[2][TR * DD];   // 40 KB, aliased for combine
    __shared__ __align__(16) float nfS[2][TR * CNODE];
    __shared__ float cM[8][4], cL[8][4];
    __shared__ float cANF[8][4][CNODE];

    int b = blockIdx.x, s = blockIdx.y;
    int tid = threadIdx.x, w = tid >> 5, lane = tid & 31;
    int g = w >> 2, rl = w & 3;
    size_t row0 = (size_t)b * NN + (size_t)s * RS;

    u64 qp[4][4];
#pragma unroll
    for (int hl = 0; hl < 4; hl++) {
        const ulonglong2* qq = (const ulonglong2*)(g_qk + ((size_t)(b * HH + g * 4 + hl)) * DD + lane * 8);
        ulonglong2 qa = qq[0], qb = qq[1];
        qp[hl][0] = qa.x; qp[hl][1] = qa.y; qp[hl][2] = qb.x; qp[hl][3] = qb.y;
    }
    float qnr[4];
#pragma unroll
    for (int hl = 0; hl < 4; hl++)
        qnr[hl] = (lane < CNODE) ? g_qn[(b * HH + g * 4 + hl) * CNODE + lane] : 0.0f;

    u64 aw[4][4];
#pragma unroll
    for (int hl = 0; hl < 4; hl++)
#pragma unroll
        for (int j = 0; j < 4; j++) aw[hl][j] = 0ull;
    float anf[4] = {0.f, 0.f, 0.f, 0.f};
    float m = 0.0f, l = 0.0f;

    {
        const float* src = enc + row0 * DD;
#pragma unroll
        for (int i = 0; i < 5; i++) { int off = (tid + i * 256) * 4; cp_async16(&encS[0][off], src + off); }
        if (tid < TR * CNODE / 4) cp_async16(&nfS[0][tid * 4], nf + row0 * CNODE + tid * 4);
        CP_COMMIT;
    }

    for (int t = 0; t < NTILES; t++) {
        int buf = t & 1;
        if (t + 1 < NTILES) {
            const float* src = enc + (row0 + (size_t)(t + 1) * TR) * DD;
#pragma unroll
            for (int i = 0; i < 5; i++) { int off = (tid + i * 256) * 4; cp_async16(&encS[buf ^ 1][off], src + off); }
            if (tid < TR * CNODE / 4)
                cp_async16(&nfS[buf ^ 1][tid * 4], nf + (row0 + (size_t)(t + 1) * TR) * CNODE + tid * 4);
            CP_COMMIT;
            CP_WAIT1;
        } else {
            CP_WAIT0;
        }
        __syncthreads();

        float tmax = -INFINITY;
#pragma unroll
        for (int k = 0; k < RPW; k++) {
            int r = rl + 4 * k;
            const ulonglong2* e2 = (const ulonglong2*)(&encS[buf][r * DD + lane * 8]);
            ulonglong2 eA = e2[0], eB = e2[1];
            float nfv = (lane < CNODE) ? nfS[buf][r * CNODE + lane] : 0.0f;

            float sacc[4];
#pragma unroll
            for (int hl = 0; hl < 4; hl++) {
                u64 acc2 = mul2(eA.x, qp[hl][0]);
                acc2 = fma2(eA.y, qp[hl][1], acc2);
                acc2 = fma2(eB.x, qp[hl][2], acc2);
                acc2 = fma2(eB.y, qp[hl][3], acc2);
                sacc[hl] = hsum2(acc2) + nfv * qnr[hl];
            }
            float v01 = (lane & 1) ? sacc[1] : sacc[0];
            float o01 = (lane & 1) ? sacc[0] : sacc[1];
            v01 += __shfl_xor_sync(FULLM, o01, 1);
            float v23 = (lane & 1) ? sacc[3] : sacc[2];
            float o23 = (lane & 1) ? sacc[2] : sacc[3];
            v23 += __shfl_xor_sync(FULLM, o23, 1);
            float vv = (lane & 2) ? v23 : v01;
            float oo = (lane & 2) ? v01 : v23;
            vv += __shfl_xor_sync(FULLM, oo, 2);
            vv += __shfl_xor_sync(FULLM, vv, 4);
            vv += __shfl_xor_sync(FULLM, vv, 8);
            vv += __shfl_xor_sync(FULLM, vv, 16);
            float p = vv;

            tmax = fmaxf(tmax, p);
            float wv = __expf(p - m);   // stale m: corrected at tile end
            l += wv;
            float w0 = __shfl_sync(FULLM, wv, 0);
            float w1 = __shfl_sync(FULLM, wv, 1);
            float w2 = __shfl_sync(FULLM, wv, 2);
            float w3 = __shfl_sync(FULLM, wv, 3);
            u64 wp0 = pk2(w0, w0), wp1 = pk2(w1, w1), wp2 = pk2(w2, w2), wp3 = pk2(w3, w3);
            aw[0][0] = fma2(eA.x, wp0, aw[0][0]); aw[0][1] = fma2(eA.y, wp0, aw[0][1]);
            aw[0][2] = fma2(eB.x, wp0, aw[0][2]); aw[0][3] = fma2(eB.y, wp0, aw[0][3]);
            aw[1][0] = fma2(eA.x, wp1, aw[1][0]); aw[1][1] = fma2(eA.y, wp1, aw[1][1]);
            aw[1][2] = fma2(eB.x, wp1, aw[1][2]); aw[1][3] = fma2(eB.y, wp1, aw[1][3]);
            aw[2][0] = fma2(eA.x, wp2, aw[2][0]); aw[2][1] = fma2(eA.y, wp2, aw[2][1]);
            aw[2][2] = fma2(eB.x, wp2, aw[2][2]); aw[2][3] = fma2(eB.y, wp2, aw[2][3]);
            aw[3][0] = fma2(eA.x, wp3, aw[3][0]); aw[3][1] = fma2(eA.y, wp3, aw[3][1]);
            aw[3][2] = fma2(eB.x, wp3, aw[3][2]); aw[3][3] = fma2(eB.y, wp3, aw[3][3]);
            anf[0] += w0 * nfv; anf[1] += w1 * nfv; anf[2] += w2 * nfv; anf[3] += w3 * nfv;
        }

        {
            float mn = fmaxf(m, tmax);
            float c = __expf(m - mn);
            m = mn;
            l *= c;
            float cc0 = __shfl_sync(FULLM, c, 0);
            float cc1 = __shfl_sync(FULLM, c, 1);
            float cc2 = __shfl_sync(FULLM, c, 2);
            float cc3 = __shfl_sync(FULLM, c, 3);
            u64 cp0 = pk2(cc0, cc0), cp1 = pk2(cc1, cc1);
            u64 cp2 = pk2(cc2, cc2), cp3 = pk2(cc3, cc3);
#pragma unroll
            for (int j = 0; j < 4; j++) {
                aw[0][j] = mul2(aw[0][j], cp0);
                aw[1][j] = mul2(aw[1][j], cp1);
                aw[2][j] = mul2(aw[2][j], cp2);
                aw[3][j] = mul2(aw[3][j], cp3);
            }
            anf[0] *= cc0; anf[1] *= cc1; anf[2] *= cc2; anf[3] *= cc3;
        }
        __syncthreads();
    }

    // ---- block combine -> split partials ----
    u64* cAW = (u64*)encS;
    if (lane < 4) { cM[w][lane] = m; cL[w][lane] = l; }
#pragma unroll
    for (int hl = 0; hl < 4; hl++) {
#pragma unroll
        for (int j = 0; j < 4; j++) cAW[(w * 4 + hl) * (DD / 2) + lane * 4 + j] = aw[hl][j];
    }
    if (lane < CNODE) {
#pragma unroll
        for (int hl = 0; hl < 4; hl++) cANF[w][hl][lane] = anf[hl];
    }
    __syncthreads();

    {
        int h = w, g2 = h >> 2, hl2 = h & 3;
        float M = -INFINITY;
#pragma unroll
        for (int rw = 0; rw < 4; rw++) M = fmaxf(M, cM[g2 * 4 + rw][hl2]);
        float es[4], L = 0.0f;
#pragma unroll
        for (int rw = 0; rw < 4; rw++) {
            es[rw] = __expf(cM[g2 * 4 + rw][hl2] - M);
            L += cL[g2 * 4 + rw][hl2] * es[rw];
        }
        int pidx = (b * SPLIT + s) * HH + h;
        u64* dst = (u64*)g_paw + (size_t)pidx * (DD / 2) + lane * 4;
        u64 ep[4];
#pragma unroll
        for (int rw = 0; rw < 4; rw++) ep[rw] = pk2(es[rw], es[rw]);
#pragma unroll
        for (int j = 0; j < 4; j++) {
            u64 acc = 0ull;
#pragma unroll
            for (int rw = 0; rw < 4; rw++)
                acc = fma2(cAW[((g2 * 4 + rw) * 4 + hl2) * (DD / 2) + lane * 4 + j], ep[rw], acc);
            dst[j] = acc;
        }
        if (lane == 0) { g_pm[pidx] = M; g_pl[pidx] = L; }
        if (lane < CNODE) {
            float acc = 0.0f;
#pragma unroll
            for (int rw = 0; rw < 4; rw++) acc += es[rw] * cANF[g2 * 4 + rw][hl2][lane];
            g_panf[pidx * CNODE + lane] = acc;
        }
    }
}

// ---------------- K4a: combine split partials (bandwidth-shaped) ----------------
// grid (BS, HH), block 256
__global__ __launch_bounds__(256) void k4a_combine() {
    __shared__ float esS[SPLIT];
    __shared__ __align__(16) float4 sred[4][64];
    int b = blockIdx.x, h = blockIdx.y, t = threadIdx.x;

    if (t < 32) {
        float pmv = (t < SPLIT) ? g_pm[(b * SPLIT + t) * HH + h] : -INFINITY;
        float plv = (t < SPLIT) ? g_pl[(b * SPLIT + t) * HH + h] : 0.0f;
        float M = pmv;
#pragma unroll
        for (int o = 16; o > 0; o >>= 1) M = fmaxf(M, __shfl_xor_sync(FULLM, M, o));
        float e = (t < SPLIT) ? __expf(pmv - M) : 0.0f;
        float Lp = plv * e;
#pragma unroll
        for (int o = 16; o > 0; o >>= 1) Lp += __shfl_xor_sync(FULLM, Lp, o);
        float invL = 1.0f / Lp;
        if (t < SPLIT) esS[t] = e * invL;
    }
    __syncthreads();

    int q = t >> 6, d4 = t & 63;
    float4 acc = make_float4(0.f, 0.f, 0.f, 0.f);
#pragma unroll
    for (int j = 0; j < 5; j++) {
        int s = q + 4 * j;
        float es = esS[s];
        float4 v = ((const float4*)(g_paw + (size_t)((b * SPLIT + s) * HH + h) * DD))[d4];
        acc.x += es * v.x; acc.y += es * v.y; acc.z += es * v.z; acc.w += es * v.w;
    }
    sred[q][d4] = acc;
    __syncthreads();

    if (t < 64) {
        float4 a = sred[0][t], b2 = sred[1][t], c = sred[2][t], d = sred[3][t];
        float4 r;
        r.x = a.x + b2.x + c.x + d.x;
        r.y = a.y + b2.y + c.y + d.y;
        r.z = a.z + b2.z + c.z + d.z;
        r.w = a.w + b2.w + c.w + d.w;
        ((float4*)(g_aw + (size_t)(b * HH + h) * DD))[t] = r;
    } else if (t >= 64 && t < 64 + CNODE) {
        int c = t - 64;
        float acc2 = 0.0f;
#pragma unroll
        for (int s = 0; s < SPLIT; s++)
            acc2 += esS[s] * g_panf[((b * SPLIT + s) * HH + h) * CNODE + c];
        g_anfc[(b * HH + h) * CNODE + c] = acc2;
    }
}

// ---------------- K4b: glimpse + g2/gn (warp-GEMV, coalesced) ----------------
// grid BS, block 256
__global__ __launch_bounds__(256) void k4b_glimpse(const float* __restrict__ Wv,
                                                   const float* __restrict__ Wout,
                                                   const float* __restrict__ Wk2,
                                                   const float* __restrict__ Wn) {
    __shared__ __align__(16) float hs[DD];
    __shared__ __align__(16) float gl[DD];
    int b = blockIdx.x, t = threadIdx.x;
    int w = t >> 5, lane = t & 31;

    {
        float awr[8];
        const float4* ap = (const float4*)(g_aw + ((size_t)(b * HH + w)) * DD + lane * 8);
        float4 a0 = ap[0], a1 = ap[1];
        awr[0]=a0.x; awr[1]=a0.y; awr[2]=a0.z; awr[3]=a0.w;
        awr[4]=a1.x; awr[5]=a1.y; awr[6]=a1.z; awr[7]=a1.w;
        float anfr = (lane < CNODE) ? g_anfc[(b * HH + w) * CNODE + lane] : 0.0f;
#pragma unroll 4
        for (int o = 0; o < 32; o++) {
            int row = w * HDIM + o;
            const float4* wv4 = (const float4*)(Wv + (size_t)row * DD) + lane * 2;
            float4 v0 = wv4[0], v1 = wv4[1];
            float acc = awr[0]*v0.x + awr[1]*v0.y + awr[2]*v0.z + awr[3]*v0.w
                      + awr[4]*v1.x + awr[5]*v1.y + awr[6]*v1.z + awr[7]*v1.w;
            if (lane < CNODE) acc += anfr * Wn[(DD + row) * CNODE + lane];
#pragma unroll
            for (int o2 = 16; o2 > 0; o2 >>= 1) acc += __shfl_xor_sync(FULLM, acc, o2);
            if (lane == 0) hs[row] = acc;
        }
    }
    __syncthreads();

    {
        float hr[8];
        const float4* hp = (const float4*)hs + lane * 2;
        float4 h0 = hp[0], h1 = hp[1];
        hr[0]=h0.x; hr[1]=h0.y; hr[2]=h0.z; hr[3]=h0.w;
        hr[4]=h1.x; hr[5]=h1.y; hr[6]=h1.z; hr[7]=h1.w;
#pragma unroll 4
        for (int o = 0; o < 32; o++) {
            int row = w * 32 + o;
            const float4* wo4 = (const float4*)(Wout + (size_t)row * DD) + lane * 2;
            float4 v0 = wo4[0], v1 = wo4[1];
            float acc = hr[0]*v0.x + hr[1]*v0.y + hr[2]*v0.z + hr[3]*v0.w
                      + hr[4]*v1.x + hr[5]*v1.y + hr[6]*v1.z + hr[7]*v1.w;
#pragma unroll
            for (int o2 = 16; o2 > 0; o2 >>= 1) acc += __shfl_xor_sync(FULLM, acc, o2);
            if (lane == 0) gl[row] = acc;
        }
    }
    __syncthreads();

    float a2 = 0.0f;
#pragma unroll 8
    for (int d = 0; d < DD; d++) a2 += gl[d] * Wk2[d * DD + t];
    g_g2[b * DD + t] = a2 * INV_SQRT_D;
    if (t < CNODE) {
        float a3 = 0.0f;
#pragma unroll 8
        for (int d = 0; d < DD; d++) a3 += gl[d] * Wn[(2 * DD + d) * CNODE + t];
        g_gn[b * CNODE + t] = a3 * INV_SQRT_D;
    }
}

// ---------------- K5a: split logits -> exp directly (no max needed: |logit| <= 10) ----
// grid (BS, SPLITL), block 256; RSL=80 = 8 warps * 10 rows exactly
__global__ __launch_bounds__(256) void k5a_logits(const float* __restrict__ enc,
                                                  const float* __restrict__ nf,
                                                  const void* __restrict__ maskp) {
    __shared__ __align__(16) float g2s[DD];
    __shared__ float gns[CNODE];
    __shared__ float tls[RSL];
    __shared__ float red[256];
    int b = blockIdx.x, s = blockIdx.y;
    int tid = threadIdx.x, wid = tid >> 5, lane = tid & 31;

    g2s[tid] = g_g2[b * DD + tid];
    if (tid < CNODE) gns[tid] = g_gn[b * CNODE + tid];
    int flags = g_flags;
    __syncthreads();

    const ulonglong2* cpa = (const ulonglong2*)(g2s + lane * 4);
    const ulonglong2* cpb = (const ulonglong2*)(g2s + 128 + lane * 4);
    ulonglong2 cA = cpa[0], cB = cpb[0];
    float gnl = (lane < CNODE) ? gns[lane] : 0.0f;

    int n0 = s * RSL;
    size_t rowb = (size_t)b * NN;
#pragma unroll
    for (int base = 0; base < 10; base += 5) {
        float pv[5];
#pragma unroll
        for (int j = 0; j < 5; j++) {
            int rr = wid + 8 * (base + j);
            const ulonglong2* ea2 = (const ulonglong2*)(enc + (rowb + n0 + rr) * DD + lane * 4);
            const ulonglong2* eb2 = (const ulonglong2*)(enc + (rowb + n0 + rr) * DD + 128 + lane * 4);
            ulonglong2 ea = ea2[0], eb = eb2[0];
            u64 a2 = mul2(ea.x, cA.x); a2 = fma2(ea.y, cA.y, a2);
            a2 = fma2(eb.x, cB.x, a2); a2 = fma2(eb.y, cB.y, a2);
            pv[j] = hsum2(a2);
            if (lane < CNODE) pv[j] += nf[(rowb + n0 + rr) * CNODE + lane] * gnl;
        }
#pragma unroll
        for (int o = 16; o > 0; o >>= 1) {
#pragma unroll
            for (int j = 0; j < 5; j++) pv[j] += __shfl_xor_sync(FULLM, pv[j], o);
        }
        if (lane == 0) {
#pragma unroll
            for (int j = 0; j < 5; j++) {
                int rr = wid + 8 * (base + j);
                bool msk = read_mask(maskp, flags, rowb + n0 + rr);
                // |tanh*10| <= 10 -> exp in [4.5e-5, 2.2e4]: no overflow, max not needed
                float ex = msk ? 0.0f : __expf(TANH_CLIP * tanhf(pv[j]));
                g_tl[rowb + n0 + rr] = ex;
                tls[rr] = ex;
            }
        }
    }
    __syncthreads();

    // single block reduction: sum of exps
    float sm = 0.0f;
    for (int r = tid; r < RSL; r += 256) sm += tls[r];
    red[tid] = sm;
    __syncthreads();
    for (int st = 128; st > 0; st >>= 1) {
        if (tid < st) red[tid] += red[tid + st];
        __syncthreads();
    }
    if (tid == 0) g_psum[b * SPLITL + s] = red[0];
}

// ---------------- K5c: combine sums + scale ----------------
// grid (BS, SPLITL), block 256
__global__ __launch_bounds__(256) void k5c_norm(float* __restrict__ out) {
    __shared__ float sInv;
    int b = blockIdx.x, s = blockIdx.y, t = threadIdx.x;
    if (t < 32) {
        float sm = (t < SPLITL) ? g_psum[b * SPLITL + t] : 0.0f;
#pragma unroll
        for (int o = 16; o > 0; o >>= 1) sm += __shfl_xor_sync(FULLM, sm, o);
        if (t == 0) sInv = 1.0f / sm;
    }
    __syncthreads();
    float inv = sInv;
    int n0 = s * RSL;
    if (t < RSL) {
        size_t i = (size_t)b * NN + n0 + t;
        out[i] = g_tl[i] * inv;
    }
}

// ---------------- launch ----------------
extern "C" void kernel_launch(void* const* d_in, const int* in_sizes, int n_in,
                              void* d_out, int out_size) {
    const float* shelf = (const float*)d_in[0];
    const float* enc   = (const float*)d_in[1];
    const float* ctx   = (const float*)d_in[2];
    const float* nf    = (const float*)d_in[3];
    const float* Wk    = (const float*)d_in[4];
    const float* Wv    = (const float*)d_in[5];
    const float* Wk2   = (const float*)d_in[6];
    const float* Wq    = (const float*)d_in[7];
    const float* Wout  = (const float*)d_in[8];
    const float* Wc    = (const float*)d_in[9];
    const float* Wg    = (const float*)d_in[10];
    const float* Wn    = (const float*)d_in[11];
    const int*   cur   = (const int*)d_in[12];
    const void*  maskp = (const void*)d_in[13];
    float* out = (float*)d_out;

    { dim3 g(BS, SPLIT1); k1_sum<<<g, 256>>>(enc, maskp); }
    k2_setup<<<BS, 256>>>(shelf, ctx, Wk, Wq, Wc, Wg, Wn, cur);
    { dim3 g(BS, SPLIT);  k3_attn<<<g, 256>>>(enc, nf); }
    { dim3 g(BS, HH);     k4a_combine<<<g, 256>>>(); }
    k4b_glimpse<<<BS, 256>>>(Wv, Wout, Wk2, Wn);
    { dim3 g(BS, SPLITL); k5a_logits<<<g, 256>>>(enc, nf, maskp); }
    { dim3 g(BS, SPLITL); k5c_norm<<<g, 256>>>(out); }
}

// round 15
// speedup vs baseline: 1.4468x; 1.4468x over previous
#include <cuda_runtime.h>
#include <cuda_bf16.h>
#include <math.h>
#include <stdint.h>

// Problem constants
#define BS 128
#define NN 2000
#define DD 256
#define HH 8
#define HDIM 32
#define CCTX 64
#define CNODE 8
#define TANH_CLIP 10.0f

#define SPLIT 20          // n-splits for k3
#define RS (NN / SPLIT)   // 100 rows per k3 block
#define TR 20             // tile rows in k3
#define NTILES (RS / TR)  // 5
#define RPW (TR / 4)      // 5 rows per warp per tile

#define SPLIT1 25          // n-splits for k1
#define RPB1 (NN / SPLIT1) // 80

#define SPLITL 25         // n-splits for k5
#define RSL (NN / SPLITL) // 80 rows per k5a block (= 8 warps * 10 rows exactly)

#define INV_SQRT_HD 0.17677669529663687f   // 1/sqrt(32)
#define INV_SQRT_D  0.0625f                // 1/sqrt(256)

typedef unsigned long long u64;

// ---------------- scratch (16B aligned) ----------------
__device__ __align__(16) float g_sump[BS * SPLIT1 * DD];
__device__ __align__(16) float g_qk[BS * HH * DD];
__device__ __align__(16) float g_qn[BS * HH * CNODE];
__device__ __align__(16) float g_pm[BS * SPLIT * HH];
__device__ __align__(16) float g_pl[BS * SPLIT * HH];
__device__ __align__(16) float g_paw[BS * SPLIT * HH * DD];
__device__ __align__(16) float g_panf[BS * SPLIT * HH * CNODE];
__device__ __align__(16) float g_aw[BS * HH * DD];
__device__ __align__(16) float g_anfc[BS * HH * CNODE];
__device__ __align__(16) float g_g2[BS * DD];
__device__ __align__(16) float g_gn[BS * CNODE];
__device__ __align__(16) float g_tl[BS * NN];      // exp(clipped logit), 0 if masked
__device__ __align__(16) float g_psum[BS * SPLITL];
__device__ int g_flags;   // zero-initialized at load; atomicOr idempotent across replays

// ---------------- helpers ----------------
__device__ __forceinline__ void cp_async16(void* sdst, const void* gsrc) {
    unsigned s = (unsigned)__cvta_generic_to_shared(sdst);
    asm volatile("cp.async.cg.shared.global [%0], [%1], 16;\n" :: "r"(s), "l"(gsrc) : "memory");
}
#define CP_COMMIT asm volatile("cp.async.commit_group;\n" ::: "memory")
#define CP_WAIT1  asm volatile("cp.async.wait_group 1;\n" ::: "memory")
#define CP_WAIT0  asm volatile("cp.async.wait_group 0;\n" ::: "memory")
#define FULLM 0xffffffffu

// packed fp32x2 (Blackwell FFMA2 — PTX-only path)
__device__ __forceinline__ u64 fma2(u64 a, u64 b, u64 c) {
    u64 d; asm("fma.rn.f32x2 %0, %1, %2, %3;" : "=l"(d) : "l"(a), "l"(b), "l"(c)); return d;
}
__device__ __forceinline__ u64 mul2(u64 a, u64 b) {
    u64 d; asm("mul.rn.f32x2 %0, %1, %2;" : "=l"(d) : "l"(a), "l"(b)); return d;
}
__device__ __forceinline__ u64 pk2(float lo, float hi) {
    u64 r; asm("mov.b64 %0, {%1, %2};" : "=l"(r) : "f"(lo), "f"(hi)); return r;
}
__device__ __forceinline__ float hsum2(u64 v) {
    float lo, hi; asm("mov.b64 {%0, %1}, %2;" : "=f"(lo), "=f"(hi) : "l"(v)); return lo + hi;
}

__device__ __forceinline__ bool read_mask(const void* mp, int flags, size_t i) {
    if (flags == 0) return false;
    if (flags & 2) {
        if (flags & 1) return ((const unsigned char*)mp)[i] != 0;  // bool
        return ((const float*)mp)[i] != 0.0f;                      // float32
    }
    return ((const int*)mp)[i] != 0;                               // int32
}

// ---------------- K1: per-split partial sums of enc + mask scan ----------------
// grid (BS, SPLIT1), block 256. Front-batched 20-deep independent loads.
__global__ __launch_bounds__(256) void k1_sum(const float* __restrict__ enc,
                                              const void* __restrict__ maskp) {
    __shared__ __align__(16) float4 sred[256];
    int b = blockIdx.x, s = blockIdx.y;
    int tid = threadIdx.x;
    int c4 = tid & 63;
    int rg = tid >> 6;

    const float4* base = (const float4*)(enc + ((size_t)b * NN + (size_t)s * RPB1) * DD) + c4;
    float4 acc = make_float4(0.f, 0.f, 0.f, 0.f);
#pragma unroll
    for (int r = 0; r < RPB1 / 4; r++) {
        float4 v = base[(size_t)(rg + 4 * r) * 64];
        acc.x += v.x; acc.y += v.y; acc.z += v.z; acc.w += v.w;
    }
    sred[tid] = acc;
    __syncthreads();
    if (tid < 64) {
        float4 a = sred[tid], b1 = sred[tid + 64], c = sred[tid + 128], d = sred[tid + 192];
        float4 r;
        r.x = a.x + b1.x + c.x + d.x;
        r.y = a.y + b1.y + c.y + d.y;
        r.z = a.z + b1.z + c.z + d.z;
        r.w = a.w + b1.w + c.w + d.w;
        ((float4*)&g_sump[(b * SPLIT1 + s) * DD])[c4] = r;
    }

    size_t idx = (size_t)(b * SPLIT1 + s) * 256 + tid;
    bool nz0 = false, nz1 = false;
    if (idx < (size_t)BS * NN) {
        unsigned char v = ((const unsigned char*)maskp)[idx];
        if (v) { if ((idx & 3) == 0) nz0 = true; else nz1 = true; }
    }
    unsigned b0 = __ballot_sync(FULLM, nz0);
    unsigned b1 = __ballot_sync(FULLM, nz1);
    if ((tid & 31) == 0) {
        int f = (b0 ? 1 : 0) | (b1 ? 2 : 0);
        if (f) atomicOr(&g_flags, f);
    }
}

// ---------------- K2: per-batch setup (coalesced warp-GEMV) ----------------
// grid BS, block 256
__global__ __launch_bounds__(256) void k2_setup(const float* __restrict__ shelf,
                                                const float* __restrict__ ctx,
                                                const float* __restrict__ Wk,
                                                const float* __restrict__ Wq,
                                                const float* __restrict__ Wc,
                                                const float* __restrict__ Wg,
                                                const float* __restrict__ Wn,
                                                const int* __restrict__ cur_node) {
    __shared__ __align__(16) float Xs[2 * DD];
    __shared__ __align__(16) float Qs[DD];
    __shared__ __align__(16) float ms[DD];
    int b = blockIdx.x, t = threadIdx.x;
    int w = t >> 5, lane = t & 31;

    int cn = cur_node[b];
    Xs[t] = shelf[((size_t)b * NN + cn) * DD + t];
    float a = 0.0f;
#pragma unroll 8
    for (int c = 0; c < CCTX; c++) a += ctx[b * CCTX + c] * Wc[t * CCTX + c];
    Xs[DD + t] = a;
    float smv = 0.0f;
#pragma unroll
    for (int s = 0; s < SPLIT1; s++) smv += g_sump[(b * SPLIT1 + s) * DD + t];
    ms[t] = smv * (1.0f / NN);
    __syncthreads();

    {
        float msr[8];
        const float4* msp = (const float4*)ms + lane * 2;
        { float4 v0 = msp[0], v1 = msp[1];
          msr[0]=v0.x; msr[1]=v0.y; msr[2]=v0.z; msr[3]=v0.w;
          msr[4]=v1.x; msr[5]=v1.y; msr[6]=v1.z; msr[7]=v1.w; }
        float xr[16];
        const float4* xp = (const float4*)Xs + lane * 4;
#pragma unroll
        for (int j = 0; j < 4; j++) {
            float4 v = xp[j];
            xr[j*4+0]=v.x; xr[j*4+1]=v.y; xr[j*4+2]=v.z; xr[j*4+3]=v.w;
        }
#pragma unroll 4
        for (int o = 0; o < 32; o++) {
            int tt = w * 32 + o;
            const float4* wg4 = (const float4*)(Wg + (size_t)tt * DD) + lane * 2;
            const float4* wq4 = (const float4*)(Wq + (size_t)tt * 2 * DD) + lane * 4;
            float acc = 0.0f;
            float4 g0 = wg4[0], g1 = wg4[1];
            acc += msr[0]*g0.x + msr[1]*g0.y + msr[2]*g0.z + msr[3]*g0.w;
            acc += msr[4]*g1.x + msr[5]*g1.y + msr[6]*g1.z + msr[7]*g1.w;
#pragma unroll
            for (int j = 0; j < 4; j++) {
                float4 q4 = wq4[j];
                acc += xr[j*4+0]*q4.x + xr[j*4+1]*q4.y + xr[j*4+2]*q4.z + xr[j*4+3]*q4.w;
            }
#pragma unroll
            for (int o2 = 16; o2 > 0; o2 >>= 1) acc += __shfl_xor_sync(FULLM, acc, o2);
            if (lane == 0) Qs[tt] = acc;
        }
    }
    __syncthreads();

#pragma unroll
    for (int h = 0; h < HH; h++) {
        float a2 = 0.0f;
#pragma unroll 8
        for (int e = 0; e < HDIM; e++) a2 += Qs[h * HDIM + e] * Wk[(h * HDIM + e) * DD + t];
        g_qk[(b * HH + h) * DD + t] = a2 * INV_SQRT_HD;
    }
    if (t < HH * CNODE) {
        int h = t >> 3, c = t & 7;
        float a3 = 0.0f;
#pragma unroll 8
        for (int e = 0; e < HDIM; e++) a3 += Qs[h * HDIM + e] * Wn[(h * HDIM + e) * CNODE + c];
        g_qn[(b * HH + h) * CNODE + c] = a3 * INV_SQRT_HD;
    }
}

// ---------------- K3: split flash glimpse, deferred per-tile rescale ----------------
// grid (BS, SPLIT), block 256
__global__ __launch_bounds__(256, 2) void k3_attn(const float* __restrict__ enc,
                                                  const float* __restrict__ nf) {
    __shared__ __align__(16) float encS[2][TR * DD];   // 40 KB, aliased for combine
    __shared__ __align__(16) float nfS[2][TR * CNODE];
    __shared__ float cM[8][4], cL[8][4];
    __shared__ float cANF[8][4][CNODE];

    int b = blockIdx.x, s = blockIdx.y;
    int tid = threadIdx.x, w = tid >> 5, lane = tid & 31;
    int g = w >> 2, rl = w & 3;
    size_t row0 = (size_t)b * NN + (size_t)s * RS;

    u64 qp[4][4];
#pragma unroll
    for (int hl = 0; hl < 4; hl++) {
        const ulonglong2* qq = (const ulonglong2*)(g_qk + ((size_t)(b * HH + g * 4 + hl)) * DD + lane * 8);
        ulonglong2 qa = qq[0], qb = qq[1];
        qp[hl][0] = qa.x; qp[hl][1] = qa.y; qp[hl][2] = qb.x; qp[hl][3] = qb.y;
    }
    float qnr[4];
#pragma unroll
    for (int hl = 0; hl < 4; hl++)
        qnr[hl] = (lane < CNODE) ? g_qn[(b * HH + g * 4 + hl) * CNODE + lane] : 0.0f;

    u64 aw[4][4];
#pragma unroll
    for (int hl = 0; hl < 4; hl++)
#pragma unroll
        for (int j = 0; j < 4; j++) aw[hl][j] = 0ull;
    float anf[4] = {0.f, 0.f, 0.f, 0.f};
    float m = 0.0f, l = 0.0f;

    {
        const float* src = enc + row0 * DD;
#pragma unroll
        for (int i = 0; i < 5; i++) { int off = (tid + i * 256) * 4; cp_async16(&encS[0][off], src + off); }
        if (tid < TR * CNODE / 4) cp_async16(&nfS[0][tid * 4], nf + row0 * CNODE + tid * 4);
        CP_COMMIT;
    }

    for (int t = 0; t < NTILES; t++) {
        int buf = t & 1;
        if (t + 1 < NTILES) {
            const float* src = enc + (row0 + (size_t)(t + 1) * TR) * DD;
#pragma unroll
            for (int i = 0; i < 5; i++) { int off = (tid + i * 256) * 4; cp_async16(&encS[buf ^ 1][off], src + off); }
            if (tid < TR * CNODE / 4)
                cp_async16(&nfS[buf ^ 1][tid * 4], nf + (row0 + (size_t)(t + 1) * TR) * CNODE + tid * 4);
            CP_COMMIT;
            CP_WAIT1;
        } else {
            CP_WAIT0;
        }
        __syncthreads();

        float tmax = -INFINITY;
#pragma unroll
        for (int k = 0; k < RPW; k++) {
            int r = rl + 4 * k;
            const ulonglong2* e2 = (const ulonglong2*)(&encS[buf][r * DD + lane * 8]);
            ulonglong2 eA = e2[0], eB = e2[1];
            float nfv = (lane < CNODE) ? nfS[buf][r * CNODE + lane] : 0.0f;

            float sacc[4];
#pragma unroll
            for (int hl = 0; hl < 4; hl++) {
                u64 acc2 = mul2(eA.x, qp[hl][0]);
                acc2 = fma2(eA.y, qp[hl][1], acc2);
                acc2 = fma2(eB.x, qp[hl][2], acc2);
                acc2 = fma2(eB.y, qp[hl][3], acc2);
                sacc[hl] = hsum2(acc2) + nfv * qnr[hl];
            }
            float v01 = (lane & 1) ? sacc[1] : sacc[0];
            float o01 = (lane & 1) ? sacc[0] : sacc[1];
            v01 += __shfl_xor_sync(FULLM, o01, 1);
            float v23 = (lane & 1) ? sacc[3] : sacc[2];
            float o23 = (lane & 1) ? sacc[2] : sacc[3];
            v23 += __shfl_xor_sync(FULLM, o23, 1);
            float vv = (lane & 2) ? v23 : v01;
            float oo = (lane & 2) ? v01 : v23;
            vv += __shfl_xor_sync(FULLM, oo, 2);
            vv += __shfl_xor_sync(FULLM, vv, 4);
            vv += __shfl_xor_sync(FULLM, vv, 8);
            vv += __shfl_xor_sync(FULLM, vv, 16);
            float p = vv;

            tmax = fmaxf(tmax, p);
            float wv = __expf(p - m);   // stale m: corrected at tile end
            l += wv;
            float w0 = __shfl_sync(FULLM, wv, 0);
            float w1 = __shfl_sync(FULLM, wv, 1);
            float w2 = __shfl_sync(FULLM, wv, 2);
            float w3 = __shfl_sync(FULLM, wv, 3);
            u64 wp0 = pk2(w0, w0), wp1 = pk2(w1, w1), wp2 = pk2(w2, w2), wp3 = pk2(w3, w3);
            aw[0][0] = fma2(eA.x, wp0, aw[0][0]); aw[0][1] = fma2(eA.y, wp0, aw[0][1]);
            aw[0][2] = fma2(eB.x, wp0, aw[0][2]); aw[0][3] = fma2(eB.y, wp0, aw[0][3]);
            aw[1][0] = fma2(eA.x, wp1, aw[1][0]); aw[1][1] = fma2(eA.y, wp1, aw[1][1]);
            aw[1][2] = fma2(eB.x, wp1, aw[1][2]); aw[1][3] = fma2(eB.y, wp1, aw[1][3]);
            aw[2][0] = fma2(eA.x, wp2, aw[2][0]); aw[2][1] = fma2(eA.y, wp2, aw[2][1]);
            aw[2][2] = fma2(eB.x, wp2, aw[2][2]); aw[2][3] = fma2(eB.y, wp2, aw[2][3]);
            aw[3][0] = fma2(eA.x, wp3, aw[3][0]); aw[3][1] = fma2(eA.y, wp3, aw[3][1]);
            aw[3][2] = fma2(eB.x, wp3, aw[3][2]); aw[3][3] = fma2(eB.y, wp3, aw[3][3]);
            anf[0] += w0 * nfv; anf[1] += w1 * nfv; anf[2] += w2 * nfv; anf[3] += w3 * nfv;
        }

        {
            float mn = fmaxf(m, tmax);
            float c = __expf(m - mn);
            m = mn;
            l *= c;
            float cc0 = __shfl_sync(FULLM, c, 0);
            float cc1 = __shfl_sync(FULLM, c, 1);
            float cc2 = __shfl_sync(FULLM, c, 2);
            float cc3 = __shfl_sync(FULLM, c, 3);
            u64 cp0 = pk2(cc0, cc0), cp1 = pk2(cc1, cc1);
            u64 cp2 = pk2(cc2, cc2), cp3 = pk2(cc3, cc3);
#pragma unroll
            for (int j = 0; j < 4; j++) {
                aw[0][j] = mul2(aw[0][j], cp0);
                aw[1][j] = mul2(aw[1][j], cp1);
                aw[2][j] = mul2(aw[2][j], cp2);
                aw[3][j] = mul2(aw[3][j], cp3);
            }
            anf[0] *= cc0; anf[1] *= cc1; anf[2] *= cc2; anf[3] *= cc3;
        }
        __syncthreads();
    }

    // ---- block combine -> split partials ----
    u64* cAW = (u64*)encS;
    if (lane < 4) { cM[w][lane] = m; cL[w][lane] = l; }
#pragma unroll
    for (int hl = 0; hl < 4; hl++) {
#pragma unroll
        for (int j = 0; j < 4; j++) cAW[(w * 4 + hl) * (DD / 2) + lane * 4 + j] = aw[hl][j];
    }
    if (lane < CNODE) {
#pragma unroll
        for (int hl = 0; hl < 4; hl++) cANF[w][hl][lane] = anf[hl];
    }
    __syncthreads();

    {
        int h = w, g2 = h >> 2, hl2 = h & 3;
        float M = -INFINITY;
#pragma unroll
        for (int rw = 0; rw < 4; rw++) M = fmaxf(M, cM[g2 * 4 + rw][hl2]);
        float es[4], L = 0.0f;
#pragma unroll
        for (int rw = 0; rw < 4; rw++) {
            es[rw] = __expf(cM[g2 * 4 + rw][hl2] - M);
            L += cL[g2 * 4 + rw][hl2] * es[rw];
        }
        int pidx = (b * SPLIT + s) * HH + h;
        u64* dst = (u64*)g_paw + (size_t)pidx * (DD / 2) + lane * 4;
        u64 ep[4];
#pragma unroll
        for (int rw = 0; rw < 4; rw++) ep[rw] = pk2(es[rw], es[rw]);
#pragma unroll
        for (int j = 0; j < 4; j++) {
            u64 acc = 0ull;
#pragma unroll
            for (int rw = 0; rw < 4; rw++)
                acc = fma2(cAW[((g2 * 4 + rw) * 4 + hl2) * (DD / 2) + lane * 4 + j], ep[rw], acc);
            dst[j] = acc;
        }
        if (lane == 0) { g_pm[pidx] = M; g_pl[pidx] = L; }
        if (lane < CNODE) {
            float acc = 0.0f;
#pragma unroll
            for (int rw = 0; rw < 4; rw++) acc += es[rw] * cANF[g2 * 4 + rw][hl2][lane];
            g_panf[pidx * CNODE + lane] = acc;
        }
    }
}

// ---------------- K4a: combine split partials (bandwidth-shaped) ----------------
// grid (BS, HH), block 256
__global__ __launch_bounds__(256) void k4a_combine() {
    __shared__ float esS[SPLIT];
    __shared__ __align__(16) float4 sred[4][64];
    int b = blockIdx.x, h = blockIdx.y, t = threadIdx.x;

    if (t < 32) {
        float pmv = (t < SPLIT) ? g_pm[(b * SPLIT + t) * HH + h] : -INFINITY;
        float plv = (t < SPLIT) ? g_pl[(b * SPLIT + t) * HH + h] : 0.0f;
        float M = pmv;
#pragma unroll
        for (int o = 16; o > 0; o >>= 1) M = fmaxf(M, __shfl_xor_sync(FULLM, M, o));
        float e = (t < SPLIT) ? __expf(pmv - M) : 0.0f;
        float Lp = plv * e;
#pragma unroll
        for (int o = 16; o > 0; o >>= 1) Lp += __shfl_xor_sync(FULLM, Lp, o);
        float invL = 1.0f / Lp;
        if (t < SPLIT) esS[t] = e * invL;
    }
    __syncthreads();

    int q = t >> 6, d4 = t & 63;
    float4 acc = make_float4(0.f, 0.f, 0.f, 0.f);
#pragma unroll
    for (int j = 0; j < 5; j++) {
        int s = q + 4 * j;
        float es = esS[s];
        float4 v = ((const float4*)(g_paw + (size_t)((b * SPLIT + s) * HH + h) * DD))[d4];
        acc.x += es * v.x; acc.y += es * v.y; acc.z += es * v.z; acc.w += es * v.w;
    }
    sred[q][d4] = acc;
    __syncthreads();

    if (t < 64) {
        float4 a = sred[0][t], b2 = sred[1][t], c = sred[2][t], d = sred[3][t];
        float4 r;
        r.x = a.x + b2.x + c.x + d.x;
        r.y = a.y + b2.y + c.y + d.y;
        r.z = a.z + b2.z + c.z + d.z;
        r.w = a.w + b2.w + c.w + d.w;
        ((float4*)(g_aw + (size_t)(b * HH + h) * DD))[t] = r;
    } else if (t >= 64 && t < 64 + CNODE) {
        int c = t - 64;
        float acc2 = 0.0f;
#pragma unroll
        for (int s = 0; s < SPLIT; s++)
            acc2 += esS[s] * g_panf[((b * SPLIT + s) * HH + h) * CNODE + c];
        g_anfc[(b * HH + h) * CNODE + c] = acc2;
    }
}

// ---------------- K4b: glimpse + g2/gn (warp-GEMV, coalesced) ----------------
// grid BS, block 256
__global__ __launch_bounds__(256) void k4b_glimpse(const float* __restrict__ Wv,
                                                   const float* __restrict__ Wout,
                                                   const float* __restrict__ Wk2,
                                                   const float* __restrict__ Wn) {
    __shared__ __align__(16) float hs[DD];
    __shared__ __align__(16) float gl[DD];
    int b = blockIdx.x, t = threadIdx.x;
    int w = t >> 5, lane = t & 31;

    {
        float awr[8];
        const float4* ap = (const float4*)(g_aw + ((size_t)(b * HH + w)) * DD + lane * 8);
        float4 a0 = ap[0], a1 = ap[1];
        awr[0]=a0.x; awr[1]=a0.y; awr[2]=a0.z; awr[3]=a0.w;
        awr[4]=a1.x; awr[5]=a1.y; awr[6]=a1.z; awr[7]=a1.w;
        float anfr = (lane < CNODE) ? g_anfc[(b * HH + w) * CNODE + lane] : 0.0f;
#pragma unroll 4
        for (int o = 0; o < 32; o++) {
            int row = w * HDIM + o;
            const float4* wv4 = (const float4*)(Wv + (size_t)row * DD) + lane * 2;
            float4 v0 = wv4[0], v1 = wv4[1];
            float acc = awr[0]*v0.x + awr[1]*v0.y + awr[2]*v0.z + awr[3]*v0.w
                      + awr[4]*v1.x + awr[5]*v1.y + awr[6]*v1.z + awr[7]*v1.w;
            if (lane < CNODE) acc += anfr * Wn[(DD + row) * CNODE + lane];
#pragma unroll
            for (int o2 = 16; o2 > 0; o2 >>= 1) acc += __shfl_xor_sync(FULLM, acc, o2);
            if (lane == 0) hs[row] = acc;
        }
    }
    __syncthreads();

    {
        float hr[8];
        const float4* hp = (const float4*)hs + lane * 2;
        float4 h0 = hp[0], h1 = hp[1];
        hr[0]=h0.x; hr[1]=h0.y; hr[2]=h0.z; hr[3]=h0.w;
        hr[4]=h1.x; hr[5]=h1.y; hr[6]=h1.z; hr[7]=h1.w;
#pragma unroll 4
        for (int o = 0; o < 32; o++) {
            int row = w * 32 + o;
            const float4* wo4 = (const float4*)(Wout + (size_t)row * DD) + lane * 2;
            float4 v0 = wo4[0], v1 = wo4[1];
            float acc = hr[0]*v0.x + hr[1]*v0.y + hr[2]*v0.z + hr[3]*v0.w
                      + hr[4]*v1.x + hr[5]*v1.y + hr[6]*v1.z + hr[7]*v1.w;
#pragma unroll
            for (int o2 = 16; o2 > 0; o2 >>= 1) acc += __shfl_xor_sync(FULLM, acc, o2);
            if (lane == 0) gl[row] = acc;
        }
    }
    __syncthreads();

    float a2 = 0.0f;
#pragma unroll 8
    for (int d = 0; d < DD; d++) a2 += gl[d] * Wk2[d * DD + t];
    g_g2[b * DD + t] = a2 * INV_SQRT_D;
    if (t < CNODE) {
        float a3 = 0.0f;
#pragma unroll 8
        for (int d = 0; d < DD; d++) a3 += gl[d] * Wn[(2 * DD + d) * CNODE + t];
        g_gn[b * CNODE + t] = a3 * INV_SQRT_D;
    }
}

// ---------------- K5a: split logits -> exp directly (no max needed: |logit| <= 10) ----
// grid (BS, SPLITL), block 256; RSL=80 = 8 warps * 10 rows exactly
__global__ __launch_bounds__(256) void k5a_logits(const float* __restrict__ enc,
                                                  const float* __restrict__ nf,
                                                  const void* __restrict__ maskp) {
    __shared__ __align__(16) float g2s[DD];
    __shared__ float gns[CNODE];
    __shared__ float tls[RSL];
    __shared__ float red[256];
    int b = blockIdx.x, s = blockIdx.y;
    int tid = threadIdx.x, wid = tid >> 5, lane = tid & 31;

    g2s[tid] = g_g2[b * DD + tid];
    if (tid < CNODE) gns[tid] = g_gn[b * CNODE + tid];
    int flags = g_flags;
    __syncthreads();

    const ulonglong2* cpa = (const ulonglong2*)(g2s + lane * 4);
    const ulonglong2* cpb = (const ulonglong2*)(g2s + 128 + lane * 4);
    ulonglong2 cA = cpa[0], cB = cpb[0];
    float gnl = (lane < CNODE) ? gns[lane] : 0.0f;

    int n0 = s * RSL;
    size_t rowb = (size_t)b * NN;
#pragma unroll
    for (int base = 0; base < 10; base += 5) {
        float pv[5];
#pragma unroll
        for (int j = 0; j < 5; j++) {
            int rr = wid + 8 * (base + j);
            const ulonglong2* ea2 = (const ulonglong2*)(enc + (rowb + n0 + rr) * DD + lane * 4);
            const ulonglong2* eb2 = (const ulonglong2*)(enc + (rowb + n0 + rr) * DD + 128 + lane * 4);
            ulonglong2 ea = ea2[0], eb = eb2[0];
            u64 a2 = mul2(ea.x, cA.x); a2 = fma2(ea.y, cA.y, a2);
            a2 = fma2(eb.x, cB.x, a2); a2 = fma2(eb.y, cB.y, a2);
            pv[j] = hsum2(a2);
            if (lane < CNODE) pv[j] += nf[(rowb + n0 + rr) * CNODE + lane] * gnl;
        }
#pragma unroll
        for (int o = 16; o > 0; o >>= 1) {
#pragma unroll
            for (int j = 0; j < 5; j++) pv[j] += __shfl_xor_sync(FULLM, pv[j], o);
        }
        if (lane == 0) {
#pragma unroll
            for (int j = 0; j < 5; j++) {
                int rr = wid + 8 * (base + j);
                bool msk = read_mask(maskp, flags, rowb + n0 + rr);
                // |tanh*10| <= 10 -> exp in [4.5e-5, 2.2e4]: no overflow, max not needed
                float ex = msk ? 0.0f : __expf(TANH_CLIP * tanhf(pv[j]));
                g_tl[rowb + n0 + rr] = ex;
                tls[rr] = ex;
            }
        }
    }
    __syncthreads();

    // single block reduction: sum of exps
    float sm = 0.0f;
    for (int r = tid; r < RSL; r += 256) sm += tls[r];
    red[tid] = sm;
    __syncthreads();
    for (int st = 128; st > 0; st >>= 1) {
        if (tid < st) red[tid] += red[tid + st];
        __syncthreads();
    }
    if (tid == 0) g_psum[b * SPLITL + s] = red[0];
}

// ---------------- K5c: combine sums + scale ----------------
// grid (BS, SPLITL), block 256
__global__ __launch_bounds__(256) void k5c_norm(float* __restrict__ out) {
    __shared__ float sInv;
    int b = blockIdx.x, s = blockIdx.y, t = threadIdx.x;
    if (t < 32) {
        float sm = (t < SPLITL) ? g_psum[b * SPLITL + t] : 0.0f;
#pragma unroll
        for (int o = 16; o > 0; o >>= 1) sm += __shfl_xor_sync(FULLM, sm, o);
        if (t == 0) sInv = 1.0f / sm;
    }
    __syncthreads();
    float inv = sInv;
    int n0 = s * RSL;
    if (t < RSL) {
        size_t i = (size_t)b * NN + n0 + t;
        out[i] = g_tl[i] * inv;
    }
}

// ---------------- launch ----------------
extern "C" void kernel_launch(void* const* d_in, const int* in_sizes, int n_in,
                              void* d_out, int out_size) {
    const float* shelf = (const float*)d_in[0];
    const float* enc   = (const float*)d_in[1];
    const float* ctx   = (const float*)d_in[2];
    const float* nf    = (const float*)d_in[3];
    const float* Wk    = (const float*)d_in[4];
    const float* Wv    = (const float*)d_in[5];
    const float* Wk2   = (const float*)d_in[6];
    const float* Wq    = (const float*)d_in[7];
    const float* Wout  = (const float*)d_in[8];
    const float* Wc    = (const float*)d_in[9];
    const float* Wg    = (const float*)d_in[10];
    const float* Wn    = (const float*)d_in[11];
    const int*   cur   = (const int*)d_in[12];
    const void*  maskp = (const void*)d_in[13];
    float* out = (float*)d_out;

    { dim3 g(BS, SPLIT1); k1_sum<<<g, 256>>>(enc, maskp); }
    k2_setup<<<BS, 256>>>(shelf, ctx, Wk, Wq, Wc, Wg, Wn, cur);
    { dim3 g(BS, SPLIT);  k3_attn<<<g, 256>>>(enc, nf); }
    { dim3 g(BS, HH);     k4a_combine<<<g, 256>>>(); }
    k4b_glimpse<<<BS, 256>>>(Wv, Wout, Wk2, Wn);
    { dim3 g(BS, SPLITL); k5a_logits<<<g, 256>>>(enc, nf, maskp); }
    { dim3 g(BS, SPLITL); k5c_norm<<<g, 256>>>(out); }
}